// round 14
// baseline (speedup 1.0000x reference)
#include <cuda_runtime.h>
#include <cstdint>

#define B_    32
#define T_    128
#define NIN_  64
#define H_    512
#define DMAX_ 50
#define K_    4
#define HB_   128           // h per block
#define NHB_  (H_/HB_)      // 4 h-tiles
#define THREADS 256
#define NBLK  (B_ * NHB_)   // 128 blocks = one wave

#define TPAD  138                 // 128 real rows + clamp/dump rows (<=137 used)
#define CAP_  32                  // event-list capacity per column

// ---- global scratch (device globals: allocation-free) ----
__device__ float g_partials[B_ * NHB_ * K_];
__device__ unsigned int g_counter = 0;

__global__ __launch_bounds__(THREADS, 1)
void snn_main_kernel(const float* __restrict__ spikes,     // [B,T,NIN]
                     const float* __restrict__ w_ih,       // [H,NIN]
                     const float* __restrict__ delay_raw,  // [H,NIN]
                     const float* __restrict__ w_read,     // [H]
                     const float* __restrict__ b_read,     // scalar
                     const float* __restrict__ slot_mask,  // [K,T]
                     float* __restrict__ out)              // [B,K]
{
    extern __shared__ char smem_raw[];
    // two scalar accumulator copies: [TPAD][HB] floats each
    float* I2 = (float*)smem_raw;                                     // 2*138*128*4 = 141312 B
    unsigned long long* wpu = (unsigned long long*)(I2 + 2*TPAD*HB_); // [NIN][HB] swizzled 65536 B
    unsigned char* s_sh = (unsigned char*)(wpu + NIN_*HB_);           // [NIN][HB] swizzled  8192 B
    unsigned char* tpos = s_sh + NIN_*HB_;                            // [NIN][CAP_]         2048 B
    unsigned long long* colbits = (unsigned long long*)(tpos + NIN_*CAP_); // [2][NIN]       1024 B
    unsigned int* maskA = (unsigned int*)(colbits + 2*NIN_);          // [T][2]              1024 B
    unsigned int* kcnt  = maskA + T_*2;                               // [NIN]                256 B
    unsigned int* maskS = kcnt + NIN_;                                // [K][4]                64 B
    float* red          = (float*)(maskS + K_*4);                     // 16 floats             64 B

    __shared__ int is_last;

    const int tid = threadIdx.x;
    const int hb  = blockIdx.x;
    const int b   = blockIdx.y;

    // ================= taps IN-BLOCK (cheap with __expf = 1 MUFU) =================
    // Coalesced LDG over [hh][ii]; swizzled STS: sw = ii*HB + ((hh+ii)&127)
    // (write: lanes have consecutive ii -> banks step by 2 -> ~2-way;
    //  phase-B read at fixed ci: lanes h -> permutation -> conflict-free).
    {
        const int gbase = hb * HB_ * NIN_;
        #pragma unroll
        for (int rep = 0; rep < (HB_*NIN_)/THREADS; rep++) {
            int idx = rep*THREADS + tid;
            int hh = idx >> 6;
            int ii = idx & 63;
            float raw  = delay_raw[gbase + idx];
            float w    = w_ih[gbase + idx];
            float d    = (float)DMAX_ / (1.f + __expf(-raw));  // sigmoid * DMAX
            float d0   = floorf(d);
            float frac = d - d0;
            int   i0   = (int)d0;
            int   s0   = i0 + 1;                             // read-before-insert => +1
            float w0 = w * (1.f - frac), w1 = w * frac;
            bool  cap = (i0 >= DMAX_);                       // i1==i0: fold both taps
            float wx = cap ? (w0 + w1) : w0;
            float wy = cap ? 0.f : w1;
            int sw = ii*HB_ + ((hh + ii) & (HB_-1));
            wpu[sw]  = ((unsigned long long)__float_as_uint(wy) << 32)
                     | (unsigned long long)__float_as_uint(wx);
            s_sh[sw] = (unsigned char)s0;
        }
    }

    // ================= events IN-BLOCK (ballots over this block's batch) ===========
    {
        const float* xb = spikes + (size_t)b * T_ * NIN_;
        #pragma unroll
        for (int rep = 0; rep < (T_*NIN_)/THREADS; rep++) {
            int idx = rep*THREADS + tid;           // t = idx>>6, i = idx&63
            float v = xb[idx];
            unsigned int ball = __ballot_sync(0xFFFFFFFFu, v != 0.f);
            if ((tid & 31) == 0) maskA[idx >> 5] = ball;
        }
        // slot mask -> 4x128-bit bitmask
        #pragma unroll
        for (int rep = 0; rep < (K_*T_)/THREADS; rep++) {
            int idx = rep*THREADS + tid;
            float v = slot_mask[idx];
            unsigned int ball = __ballot_sync(0xFFFFFFFFu, v != 0.f);
            if ((tid & 31) == 0) maskS[idx >> 5] = ball;
        }
    }

    // ---- zero both I copies ----
    {
        float4* I4 = (float4*)I2;
        for (int r = tid; r < (2*TPAD*HB_)/4; r += THREADS)
            I4[r] = make_float4(0.f, 0.f, 0.f, 0.f);
    }
    __syncthreads();

    // ---- bit-transpose -> per-column masks ----
    if (tid < 2*NIN_) {
        int i    = tid & (NIN_-1);
        int half = tid >> 6;
        int wsel = i >> 5;
        int shft = i & 31;
        unsigned long long bits = 0ull;
        #pragma unroll
        for (int tb = 0; tb < 64; tb++) {
            unsigned int mw = maskA[(half*64 + tb)*2 + wsel];
            bits |= (unsigned long long)((mw >> shft) & 1u) << tb;
        }
        colbits[half*NIN_ + i] = bits;
    }
    __syncthreads();

    // ---- decode set-bit positions per column ----
    if (tid < NIN_) {
        int ci = tid;
        unsigned long long lo = colbits[ci];
        unsigned long long hi = colbits[NIN_ + ci];
        int k = __popcll(lo) + __popcll(hi);
        kcnt[ci] = (unsigned int)k;
        unsigned char loc[CAP_];
        #pragma unroll
        for (int j = 0; j < CAP_; j++) loc[j] = 0xFF;
        int n = 0;
        unsigned long long m = lo;
        while (m && n < CAP_) { int p = __ffsll(m) - 1; m &= m - 1; loc[n++] = (unsigned char)p; }
        m = hi;
        while (m && n < CAP_) { int p = __ffsll(m) - 1; m &= m - 1; loc[n++] = (unsigned char)(64 + p); }
        unsigned long long* dst = (unsigned long long*)(tpos + ci*CAP_);
        const unsigned long long* src = (const unsigned long long*)loc;
        #pragma unroll
        for (int j = 0; j < CAP_/8; j++) dst[j] = src[j];
    }
    __syncthreads();

    // ---- Phase B: event-list scatter on ALL 8 warps ----
    // Group A (warps 0-3): columns 0..31 -> copy A. Group B (warps 4-7): columns
    // 32..63 -> copy B. Same h range, separate copies -> no races, deterministic
    // per-thread order. Within a column tap0 target rows are strictly increasing
    // (same shift, distinct bits; clamps 128+j increasing) -> batch-8 rows distinct
    // -> load-first safe. Tap1 rows = tap0 rows + 1 (distinct likewise); cross-sub-
    // batch aliasing handled by program order. Sentinel 0xFF lands in dump rows.
    {
        const int grp = tid >> 7;
        const int h   = tid & (HB_-1);
        float* __restrict__ Ic = I2 + grp * (TPAD*HB_);
        const int cbase = grp * 32;
        #pragma unroll 1
        for (int cc = 0; cc < 32; cc++) {
            const int ci = cbase + cc;
            const int sw = ci*HB_ + ((h + ci) & (HB_-1));
            const unsigned long long wb = wpu[sw];
            const float wx = __uint_as_float((unsigned int)(wb & 0xFFFFFFFFull));
            const float wy = __uint_as_float((unsigned int)(wb >> 32));
            const int s0 = (int)s_sh[sw];
            const int k  = (int)kcnt[ci];
            const int kb = min(k, CAP_);
            const unsigned char* tp = tpos + ci*CAP_;
            #pragma unroll 1
            for (int e = 0; e < kb; e += 8) {
                uint2 p8 = *(const uint2*)(tp + e);
                int o0 = min((int)(p8.x & 255u)         + s0, T_ + 0)*HB_ + h;
                int o1 = min((int)((p8.x >> 8) & 255u)  + s0, T_ + 1)*HB_ + h;
                int o2 = min((int)((p8.x >> 16) & 255u) + s0, T_ + 2)*HB_ + h;
                int o3 = min((int)(p8.x >> 24)          + s0, T_ + 3)*HB_ + h;
                int o4 = min((int)(p8.y & 255u)         + s0, T_ + 4)*HB_ + h;
                int o5 = min((int)((p8.y >> 8) & 255u)  + s0, T_ + 5)*HB_ + h;
                int o6 = min((int)((p8.y >> 16) & 255u) + s0, T_ + 6)*HB_ + h;
                int o7 = min((int)(p8.y >> 24)          + s0, T_ + 7)*HB_ + h;
                // tap0 sub-batch
                float a0 = Ic[o0]; float a1 = Ic[o1]; float a2 = Ic[o2]; float a3 = Ic[o3];
                float a4 = Ic[o4]; float a5 = Ic[o5]; float a6 = Ic[o6]; float a7 = Ic[o7];
                Ic[o0] = a0 + wx; Ic[o1] = a1 + wx; Ic[o2] = a2 + wx; Ic[o3] = a3 + wx;
                Ic[o4] = a4 + wx; Ic[o5] = a5 + wx; Ic[o6] = a6 + wx; Ic[o7] = a7 + wx;
                // tap1 sub-batch (rows +1)
                float c0 = Ic[o0+HB_]; float c1 = Ic[o1+HB_]; float c2 = Ic[o2+HB_]; float c3 = Ic[o3+HB_];
                float c4 = Ic[o4+HB_]; float c5 = Ic[o5+HB_]; float c6 = Ic[o6+HB_]; float c7 = Ic[o7+HB_];
                Ic[o0+HB_] = c0 + wy; Ic[o1+HB_] = c1 + wy; Ic[o2+HB_] = c2 + wy; Ic[o3+HB_] = c3 + wy;
                Ic[o4+HB_] = c4 + wy; Ic[o5+HB_] = c5 + wy; Ic[o6+HB_] = c6 + wy; Ic[o7+HB_] = c7 + wy;
            }
            if (k > CAP_) {                      // exact fallback, ~never taken
                unsigned long long lo = colbits[ci], hi2 = colbits[NIN_ + ci];
                int rem = CAP_;
                while (rem && lo)  { lo  &= lo  - 1; rem--; }
                while (rem && hi2) { hi2 &= hi2 - 1; rem--; }
                while (lo)  { int t = __ffsll(lo) - 1;      lo  &= lo  - 1;
                              int r = min(t + s0, T_);
                              Ic[r*HB_ + h] += wx; Ic[(r+1)*HB_ + h] += wy; }
                while (hi2) { int t = 64 + __ffsll(hi2) - 1; hi2 &= hi2 - 1;
                              int r = min(t + s0, T_);
                              Ic[r*HB_ + h] += wx; Ic[(r+1)*HB_ + h] += wy; }
            }
        }
    }
    __syncthreads();

    // ---- Phase 3: LIF scan (I[t] = A[t][h] + B[t][h]), popcount readout ----
    if (tid < HB_) {
        float v = 0.f;       // VRESET
        int   ref = 0;
        unsigned int sb0 = 0u, sb1 = 0u, sb2 = 0u, sb3 = 0u;
        #pragma unroll
        for (int t = 0; t < T_; t++) {
            float I  = I2[t*HB_ + tid] + I2[TPAD*HB_ + t*HB_ + tid];
            bool  nr = (ref <= 0);
            float vn = nr ? (v + 0.1f * (I - v)) : v;            // DT/TAU=0.1, VRESET=0
            bool  spk = nr && (vn - 1.0f >= 0.f);                // spike_fn(v-THR)*not_ref
            v   = spk ? 0.f : vn;
            ref = spk ? 2 : max(ref - 1, 0);
            unsigned int bit = spk ? 1u : 0u;
            if (t < 32)       sb0 |= bit << t;
            else if (t < 64)  sb1 |= bit << (t - 32);
            else if (t < 96)  sb2 |= bit << (t - 64);
            else              sb3 |= bit << (t - 96);
        }

        float wr = w_read[hb*HB_ + tid];
        int n0 = __popc(sb0 & maskS[0])  + __popc(sb1 & maskS[1])
               + __popc(sb2 & maskS[2])  + __popc(sb3 & maskS[3]);
        int n1 = __popc(sb0 & maskS[4])  + __popc(sb1 & maskS[5])
               + __popc(sb2 & maskS[6])  + __popc(sb3 & maskS[7]);
        int n2 = __popc(sb0 & maskS[8])  + __popc(sb1 & maskS[9])
               + __popc(sb2 & maskS[10]) + __popc(sb3 & maskS[11]);
        int n3 = __popc(sb0 & maskS[12]) + __popc(sb1 & maskS[13])
               + __popc(sb2 & maskS[14]) + __popc(sb3 & maskS[15]);
        float c0 = (float)n0 * wr;
        float c1 = (float)n1 * wr;
        float c2 = (float)n2 * wr;
        float c3 = (float)n3 * wr;
        #pragma unroll
        for (int off = 16; off; off >>= 1) {
            c0 += __shfl_down_sync(0xFFFFFFFFu, c0, off);
            c1 += __shfl_down_sync(0xFFFFFFFFu, c1, off);
            c2 += __shfl_down_sync(0xFFFFFFFFu, c2, off);
            c3 += __shfl_down_sync(0xFFFFFFFFu, c3, off);
        }
        int lane = tid & 31, warp = tid >> 5;   // warps 0..3
        if (lane == 0) {
            red[warp*4 + 0] = c0;
            red[warp*4 + 1] = c1;
            red[warp*4 + 2] = c2;
            red[warp*4 + 3] = c3;
        }
    }
    __syncthreads();
    if (tid < K_) {
        float s = red[tid] + red[4 + tid] + red[8 + tid] + red[12 + tid];
        g_partials[(b*NHB_ + hb)*K_ + tid] = s;
    }
    __syncthreads();

    // ---- fused deterministic final reduction: last block writes output ----
    if (tid == 0) {
        __threadfence();
        unsigned int done = atomicAdd(&g_counter, 1u);
        is_last = (done == NBLK - 1) ? 1 : 0;
    }
    __syncthreads();
    if (is_last) {
        if (tid == 0) g_counter = 0;   // reset for next graph replay
        __threadfence();
        if (tid < B_ * K_) {
            int bb = tid >> 2, kk = tid & 3;
            float s = b_read[0];
            #pragma unroll
            for (int h2 = 0; h2 < NHB_; h2++)
                s += __ldcg(&g_partials[(bb*NHB_ + h2)*K_ + kk]);
            out[bb*K_ + kk] = s;
        }
    }
}

extern "C" void kernel_launch(void* const* d_in, const int* in_sizes, int n_in,
                              void* d_out, int out_size)
{
    (void)in_sizes; (void)n_in; (void)out_size;
    const float* spikes    = (const float*)d_in[0];   // [32,128,64]
    const float* w_ih      = (const float*)d_in[1];   // [512,64]
    const float* delay_raw = (const float*)d_in[2];   // [512,64]
    const float* w_read    = (const float*)d_in[3];   // [512]
    const float* b_read    = (const float*)d_in[4];   // scalar
    const float* slot_mask = (const float*)d_in[5];   // [4,128]

    const size_t SMEM = (size_t)2*TPAD*HB_*4          // 2 I copies   141312
                      + (size_t)NIN_*HB_*8            // wpu           65536
                      + (size_t)NIN_*HB_              // s (u8)         8192
                      + (size_t)NIN_*CAP_             // tpos           2048
                      + (size_t)2*NIN_*8              // colbits        1024
                      + (size_t)T_*2*4                // maskA          1024
                      + (size_t)NIN_*4                // kcnt            256
                      + (size_t)K_*4*4                // maskS            64
                      + 16*4;                         // red              64
    cudaFuncSetAttribute(snn_main_kernel,
                         cudaFuncAttributeMaxDynamicSharedMemorySize, (int)SMEM);

    dim3 grid(NHB_, B_);
    snn_main_kernel<<<grid, THREADS, SMEM>>>(spikes, w_ih, delay_raw, w_read,
                                             b_read, slot_mask, (float*)d_out);
}

// round 16
// speedup vs baseline: 1.2545x; 1.2545x over previous
#include <cuda_runtime.h>
#include <cstdint>

#define B_    32
#define T_    128
#define NIN_  64
#define H_    512
#define DMAX_ 50
#define K_    4
#define HB_   128           // h per block
#define NHB_  (H_/HB_)      // 4 h-tiles
#define THREADS 256
#define NBLK  (B_ * NHB_)   // 128 blocks = one wave

#define TPAD  138                 // 128 real rows + clamp/dump rows (<=136 used)
#define CAP_  32                  // event-list capacity per column
#define BAR_TARGET NBLK           // 128 tap arrivals (events in-block)

// ---- global scratch (device globals: allocation-free) ----
__device__ unsigned long long g_wpu[NIN_ * H_];   // (wx,wy) packed, [i][h_global]
__device__ unsigned char     g_s  [NIN_ * H_];    // shift s0, [i][h_global]
__device__ float g_partials[B_ * NHB_ * K_];
__device__ unsigned int g_counter = 0;
__device__ unsigned int g_bar = 0;

__global__ __launch_bounds__(THREADS, 1)
void snn_main_kernel(const float* __restrict__ spikes,     // [B,T,NIN]
                     const float* __restrict__ w_ih,       // [H,NIN]
                     const float* __restrict__ delay_raw,  // [H,NIN]
                     const float* __restrict__ w_read,     // [H]
                     const float* __restrict__ b_read,     // scalar
                     const float* __restrict__ slot_mask,  // [K,T]
                     float* __restrict__ out)              // [B,K]
{
    extern __shared__ char smem_raw[];
    // two scalar accumulator copies: [TPAD][HB] floats each
    float* I2 = (float*)smem_raw;                                     // 141312 B
    unsigned long long* wpu = (unsigned long long*)(I2 + 2*TPAD*HB_); // [NIN][HB]  65536 B
    unsigned char* s_sh = (unsigned char*)(wpu + NIN_*HB_);           // [NIN][HB]   8192 B
    unsigned short* tpos = (unsigned short*)(s_sh + NIN_*HB_);        // [NIN][CAP_] u16 premul 4096 B
    unsigned long long* colbits = (unsigned long long*)(tpos + NIN_*CAP_); // [2][NIN] 1024 B
    unsigned int* maskA = (unsigned int*)(colbits + 2*NIN_);          // [T][2]      1024 B
    unsigned int* kcnt  = maskA + T_*2;                               // [NIN]        256 B
    unsigned int* maskS = kcnt + NIN_;                                // [K][4]        64 B
    float* red          = (float*)(maskS + K_*4);                     // 16 floats     64 B

    __shared__ int is_last;

    const int tid = threadIdx.x;
    const int hb  = blockIdx.x;
    const int b   = blockIdx.y;
    const int blin = b * NHB_ + hb;     // 0..127

    // ================= P0: distributed tap params, 1 exp per thread =================
    {
        int idx = blin * THREADS + tid;              // 0..32767 over [h][i] h-major
        int h = idx >> 6;
        int i = idx & 63;
        float raw  = delay_raw[idx];
        float w    = w_ih[idx];
        float d    = (float)DMAX_ / (1.f + __expf(-raw));  // sigmoid * DMAX
        float d0   = floorf(d);
        float frac = d - d0;
        int   i0   = (int)d0;
        int   s0   = i0 + 1;                             // read-before-insert => +1
        float w0 = w * (1.f - frac), w1 = w * frac;
        bool  cap = (i0 >= DMAX_);                       // i1==i0: fold both taps
        float wx = cap ? (w0 + w1) : w0;
        float wy = cap ? 0.f : w1;
        g_wpu[i*H_ + h] = ((unsigned long long)__float_as_uint(wy) << 32)
                        | (unsigned long long)__float_as_uint(wx);
        g_s  [i*H_ + h] = (unsigned char)s0;
    }
    __syncthreads();
    if (tid == 0) { __threadfence(); atomicAdd(&g_bar, 1u); }

    // ================= events IN-BLOCK (ballots over this block's batch) ===========
    {
        const float* xb = spikes + (size_t)b * T_ * NIN_;
        #pragma unroll
        for (int rep = 0; rep < (T_*NIN_)/THREADS; rep++) {
            int idx = rep*THREADS + tid;           // t = idx>>6, i = idx&63
            float v = xb[idx];
            unsigned int ball = __ballot_sync(0xFFFFFFFFu, v != 0.f);
            if ((tid & 31) == 0) maskA[idx >> 5] = ball;
        }
        // slot mask -> 4x128-bit bitmask
        #pragma unroll
        for (int rep = 0; rep < (K_*T_)/THREADS; rep++) {
            int idx = rep*THREADS + tid;
            float v = slot_mask[idx];
            unsigned int ball = __ballot_sync(0xFFFFFFFFu, v != 0.f);
            if ((tid & 31) == 0) maskS[idx >> 5] = ball;
        }
    }

    // ---- independent work while tap producers finish: zero both I copies ----
    {
        float4* I4 = (float4*)I2;
        for (int r = tid; r < (2*TPAD*HB_)/4; r += THREADS)
            I4[r] = make_float4(0.f, 0.f, 0.f, 0.f);
    }
    __syncthreads();

    // ---- bit-transpose -> per-column masks ----
    if (tid < 2*NIN_) {
        int i    = tid & (NIN_-1);
        int half = tid >> 6;
        int wsel = i >> 5;
        int shft = i & 31;
        unsigned long long bits = 0ull;
        #pragma unroll
        for (int tb = 0; tb < 64; tb++) {
            unsigned int mw = maskA[(half*64 + tb)*2 + wsel];
            bits |= (unsigned long long)((mw >> shft) & 1u) << tb;
        }
        colbits[half*NIN_ + i] = bits;
    }
    __syncthreads();

    // ---- decode set-bit positions per column: PREMULTIPLIED u16 (t'*128) ----
    if (tid < NIN_) {
        int ci = tid;
        unsigned long long lo = colbits[ci];
        unsigned long long hi = colbits[NIN_ + ci];
        int k = __popcll(lo) + __popcll(hi);
        kcnt[ci] = (unsigned int)k;
        unsigned short loc[CAP_];
        #pragma unroll
        for (int j = 0; j < CAP_; j++) loc[j] = 0xFFFF;   // sentinel -> clamps to dump row
        int n = 0;
        unsigned long long m = lo;
        while (m && n < CAP_) { int p = __ffsll(m) - 1; m &= m - 1; loc[n++] = (unsigned short)(p << 7); }
        m = hi;
        while (m && n < CAP_) { int p = __ffsll(m) - 1; m &= m - 1; loc[n++] = (unsigned short)((64 + p) << 7); }
        unsigned long long* dst = (unsigned long long*)(tpos + ci*CAP_);
        const unsigned long long* src = (const unsigned long long*)loc;
        #pragma unroll
        for (int j = 0; j < (CAP_*2)/8; j++) dst[j] = src[j];
    }

    // ---- device barrier: wait for all tap slices ----
    if (tid == 0) {
        unsigned int v;
        for (;;) {
            asm volatile("ld.global.cg.u32 %0, [%1];" : "=r"(v) : "l"(&g_bar));
            if (v >= BAR_TARGET) break;
            __nanosleep(64);
        }
    }
    __syncthreads();
    __threadfence();

    // ---- stage wpu/s tiles (coalesced uint4 copies) ----
    {
        const uint4* src = (const uint4*)(g_wpu);
        uint4* dst = (uint4*)wpu;
        #pragma unroll
        for (int rep = 0; rep < (NIN_*HB_/2)/THREADS; rep++) {   // 4096 uint4
            int idx = rep*THREADS + tid;
            int i = idx >> 6;
            int c = idx & 63;
            dst[idx] = src[(i*H_ + hb*HB_)/2 + c];
        }
        const uint4* ssrc = (const uint4*)(g_s);
        uint4* sdst = (uint4*)s_sh;
        #pragma unroll
        for (int rep = 0; rep < (NIN_*HB_/16)/THREADS; rep++) {  // 512 uint4
            int idx = rep*THREADS + tid;
            int i = idx >> 3;
            int c = idx & 7;
            sdst[idx] = ssrc[(i*H_ + hb*HB_)/16 + c];
        }
    }
    __syncthreads();

    // ---- Phase B: event-list scatter on ALL 8 warps, diet addressing ----
    // Group A (warps 0-3): columns 0..31 -> copy A; group B (warps 4-7): columns
    // 32..63 -> copy B. Per slot j: o_j = min(pre_j + base, cl_j) with
    // base = s0*128+h (per column), cl_j = (128+j)*128+h (per thread). Positions
    // strictly ascend and cl_j ascends with j -> batch-8 rows pairwise distinct ->
    // loads-before-stores safe. Sentinel 0xFFFF clamps into its slot's dump row;
    // first batch is unconditional (k=0..8 all safe via sentinels).
    {
        const int grp = tid >> 7;
        const int h   = tid & (HB_-1);
        float* __restrict__ Ic = I2 + grp * (TPAD*HB_);
        const int cbase = grp * 32;
        const int cl0 = (T_+0)*HB_ + h;
        const int cl1 = (T_+1)*HB_ + h;
        const int cl2 = (T_+2)*HB_ + h;
        const int cl3 = (T_+3)*HB_ + h;
        const int cl4 = (T_+4)*HB_ + h;
        const int cl5 = (T_+5)*HB_ + h;
        const int cl6 = (T_+6)*HB_ + h;
        const int cl7 = (T_+7)*HB_ + h;

        #pragma unroll 1
        for (int cc = 0; cc < 32; cc++) {
            const int ci = cbase + cc;
            const unsigned long long wb = wpu[ci*HB_ + h];
            const float wx = __uint_as_float((unsigned int)(wb & 0xFFFFFFFFull));
            const float wy = __uint_as_float((unsigned int)(wb >> 32));
            const int base = (int)s_sh[ci*HB_ + h] * HB_ + h;
            const int k  = (int)kcnt[ci];
            const unsigned short* tp = tpos + ci*CAP_;

            auto batch8 = [&](uint4 q) {
                int o0 = min((int)(q.x & 0xFFFFu) + base, cl0);
                int o1 = min((int)(q.x >> 16)     + base, cl1);
                int o2 = min((int)(q.y & 0xFFFFu) + base, cl2);
                int o3 = min((int)(q.y >> 16)     + base, cl3);
                int o4 = min((int)(q.z & 0xFFFFu) + base, cl4);
                int o5 = min((int)(q.z >> 16)     + base, cl5);
                int o6 = min((int)(q.w & 0xFFFFu) + base, cl6);
                int o7 = min((int)(q.w >> 16)     + base, cl7);
                // tap0 sub-batch
                float a0 = Ic[o0]; float a1 = Ic[o1]; float a2 = Ic[o2]; float a3 = Ic[o3];
                float a4 = Ic[o4]; float a5 = Ic[o5]; float a6 = Ic[o6]; float a7 = Ic[o7];
                Ic[o0] = a0 + wx; Ic[o1] = a1 + wx; Ic[o2] = a2 + wx; Ic[o3] = a3 + wx;
                Ic[o4] = a4 + wx; Ic[o5] = a5 + wx; Ic[o6] = a6 + wx; Ic[o7] = a7 + wx;
                // tap1 sub-batch (rows +1)
                float c0 = Ic[o0+HB_]; float c1 = Ic[o1+HB_]; float c2 = Ic[o2+HB_]; float c3 = Ic[o3+HB_];
                float c4 = Ic[o4+HB_]; float c5 = Ic[o5+HB_]; float c6 = Ic[o6+HB_]; float c7 = Ic[o7+HB_];
                Ic[o0+HB_] = c0 + wy; Ic[o1+HB_] = c1 + wy; Ic[o2+HB_] = c2 + wy; Ic[o3+HB_] = c3 + wy;
                Ic[o4+HB_] = c4 + wy; Ic[o5+HB_] = c5 + wy; Ic[o6+HB_] = c6 + wy; Ic[o7+HB_] = c7 + wy;
            };

            // unconditional first batch (slots 0..7; sentinels land in dump rows)
            batch8(*(const uint4*)(tp));

            if (k > 8) {
                const int kb = min(k, CAP_);
                #pragma unroll 1
                for (int e = 8; e < kb; e += 8)
                    batch8(*(const uint4*)(tp + e));

                if (k > CAP_) {                  // exact fallback, ~never taken
                    const int s0 = base - h;     // s0*HB_
                    unsigned long long lo = colbits[ci], hi2 = colbits[NIN_ + ci];
                    int rem = CAP_;
                    while (rem && lo)  { lo  &= lo  - 1; rem--; }
                    while (rem && hi2) { hi2 &= hi2 - 1; rem--; }
                    while (lo)  { int t = __ffsll(lo) - 1;      lo  &= lo  - 1;
                                  int o = min(t*HB_ + s0 + h, cl0);
                                  Ic[o] += wx; Ic[o + HB_] += wy; }
                    while (hi2) { int t = 64 + __ffsll(hi2) - 1; hi2 &= hi2 - 1;
                                  int o = min(t*HB_ + s0 + h, cl0);
                                  Ic[o] += wx; Ic[o + HB_] += wy; }
                }
            }
        }
    }
    __syncthreads();

    // ---- Phase 3: LIF scan (I[t] = A[t][h] + B[t][h]), popcount readout ----
    if (tid < HB_) {
        float v = 0.f;       // VRESET
        int   ref = 0;
        unsigned int sb0 = 0u, sb1 = 0u, sb2 = 0u, sb3 = 0u;
        #pragma unroll
        for (int t = 0; t < T_; t++) {
            float I  = I2[t*HB_ + tid] + I2[TPAD*HB_ + t*HB_ + tid];
            bool  nr = (ref <= 0);
            float vn = nr ? (v + 0.1f * (I - v)) : v;            // DT/TAU=0.1, VRESET=0
            bool  spk = nr && (vn - 1.0f >= 0.f);                // spike_fn(v-THR)*not_ref
            v   = spk ? 0.f : vn;
            ref = spk ? 2 : max(ref - 1, 0);
            unsigned int bit = spk ? 1u : 0u;
            if (t < 32)       sb0 |= bit << t;
            else if (t < 64)  sb1 |= bit << (t - 32);
            else if (t < 96)  sb2 |= bit << (t - 64);
            else              sb3 |= bit << (t - 96);
        }

        float wr = w_read[hb*HB_ + tid];
        int n0 = __popc(sb0 & maskS[0])  + __popc(sb1 & maskS[1])
               + __popc(sb2 & maskS[2])  + __popc(sb3 & maskS[3]);
        int n1 = __popc(sb0 & maskS[4])  + __popc(sb1 & maskS[5])
               + __popc(sb2 & maskS[6])  + __popc(sb3 & maskS[7]);
        int n2 = __popc(sb0 & maskS[8])  + __popc(sb1 & maskS[9])
               + __popc(sb2 & maskS[10]) + __popc(sb3 & maskS[11]);
        int n3 = __popc(sb0 & maskS[12]) + __popc(sb1 & maskS[13])
               + __popc(sb2 & maskS[14]) + __popc(sb3 & maskS[15]);
        float c0 = (float)n0 * wr;
        float c1 = (float)n1 * wr;
        float c2 = (float)n2 * wr;
        float c3 = (float)n3 * wr;
        #pragma unroll
        for (int off = 16; off; off >>= 1) {
            c0 += __shfl_down_sync(0xFFFFFFFFu, c0, off);
            c1 += __shfl_down_sync(0xFFFFFFFFu, c1, off);
            c2 += __shfl_down_sync(0xFFFFFFFFu, c2, off);
            c3 += __shfl_down_sync(0xFFFFFFFFu, c3, off);
        }
        int lane = tid & 31, warp = tid >> 5;   // warps 0..3
        if (lane == 0) {
            red[warp*4 + 0] = c0;
            red[warp*4 + 1] = c1;
            red[warp*4 + 2] = c2;
            red[warp*4 + 3] = c3;
        }
    }
    __syncthreads();
    if (tid < K_) {
        float s = red[tid] + red[4 + tid] + red[8 + tid] + red[12 + tid];
        g_partials[(b*NHB_ + hb)*K_ + tid] = s;
    }
    __syncthreads();

    // ---- fused deterministic final reduction: last block writes output ----
    if (tid == 0) {
        __threadfence();
        unsigned int done = atomicAdd(&g_counter, 1u);
        is_last = (done == NBLK - 1) ? 1 : 0;
    }
    __syncthreads();
    if (is_last) {
        if (tid == 0) { g_counter = 0; g_bar = 0; }   // reset for next graph replay
        __threadfence();
        if (tid < B_ * K_) {
            int bb = tid >> 2, kk = tid & 3;
            float s = b_read[0];
            #pragma unroll
            for (int h2 = 0; h2 < NHB_; h2++)
                s += __ldcg(&g_partials[(bb*NHB_ + h2)*K_ + kk]);
            out[bb*K_ + kk] = s;
        }
    }
}

extern "C" void kernel_launch(void* const* d_in, const int* in_sizes, int n_in,
                              void* d_out, int out_size)
{
    (void)in_sizes; (void)n_in; (void)out_size;
    const float* spikes    = (const float*)d_in[0];   // [32,128,64]
    const float* w_ih      = (const float*)d_in[1];   // [512,64]
    const float* delay_raw = (const float*)d_in[2];   // [512,64]
    const float* w_read    = (const float*)d_in[3];   // [512]
    const float* b_read    = (const float*)d_in[4];   // scalar
    const float* slot_mask = (const float*)d_in[5];   // [4,128]

    const size_t SMEM = (size_t)2*TPAD*HB_*4          // 2 I copies   141312
                      + (size_t)NIN_*HB_*8            // wpu           65536
                      + (size_t)NIN_*HB_              // s (u8)         8192
                      + (size_t)NIN_*CAP_*2           // tpos (u16)     4096
                      + (size_t)2*NIN_*8              // colbits        1024
                      + (size_t)T_*2*4                // maskA          1024
                      + (size_t)NIN_*4                // kcnt            256
                      + (size_t)K_*4*4                // maskS            64
                      + 16*4;                         // red              64
    cudaFuncSetAttribute(snn_main_kernel,
                         cudaFuncAttributeMaxDynamicSharedMemorySize, (int)SMEM);

    dim3 grid(NHB_, B_);
    snn_main_kernel<<<grid, THREADS, SMEM>>>(spikes, w_ih, delay_raw, w_read,
                                             b_read, slot_mask, (float*)d_out);
}